// round 2
// baseline (speedup 1.0000x reference)
#include <cuda_runtime.h>
#include <math.h>

#define NN   50000      // nodes
#define NE   800000     // edges
#define IND  50         // input dim
#define HID  256        // hidden
#define NC   121        // classes
#define XP   64         // padded x / agg1 row stride
#define AGP  128        // padded p-aggregate row stride
#define PRLS 384        // combined [p(128) | r(128) | l2(128)] row stride

// ---------------- scratch (device globals: no allocations allowed) ----------
__device__ __align__(16) float g_xpad[(size_t)NN * XP];    // x padded to 64 cols
__device__ __align__(16) float g_deg [NN];                 // in-degree (float)
__device__ __align__(16) float g_agg1[(size_t)NN * XP];    // segment_sum of x[src]
__device__ __align__(16) float g_h   [(size_t)NN * HID];   // layer-1 output
__device__ __align__(16) float g_prl [(size_t)NN * PRLS];  // p(0..120) r(128..248) l2(256..376)
__device__ __align__(16) float g_aggp[(size_t)NN * AGP];   // segment_sum of p[src]

// vector global reduction (sm_90+)
__device__ __forceinline__ void red4(float* a, float4 v) {
    asm volatile("red.global.add.v4.f32 [%0], {%1,%2,%3,%4};"
                 :: "l"(a), "f"(v.x), "f"(v.y), "f"(v.z), "f"(v.w) : "memory");
}

// ---------------- zero scratch (must be re-zeroed every replay) -------------
__global__ __launch_bounds__(256) void zero_all_kernel() {
    int i = blockIdx.x * blockDim.x + threadIdx.x;   // 1.6M threads
    float4 z = make_float4(0.f, 0.f, 0.f, 0.f);
    if (i < NN / 4)        ((float4*)g_deg )[i] = z;   // 12500
    if (i < NN * XP / 4)   ((float4*)g_agg1)[i] = z;   // 800000
    if (i < NN * AGP / 4)  ((float4*)g_aggp)[i] = z;   // 1600000
}

// ---------------- pad x into [NN, 64] ---------------------------------------
__global__ __launch_bounds__(256) void pad_x_kernel(const float* __restrict__ x) {
    int t = blockIdx.x * blockDim.x + threadIdx.x;
    if (t >= NN * XP) return;
    int row = t >> 6, c = t & 63;
    g_xpad[t] = (c < IND) ? x[row * IND + c] : 0.f;
}

// ---------------- edge scatter 1: agg1 += x_pad[src], deg += 1 --------------
// half-warp (16 lanes) per edge; lanes 0..12 move 13 float4 (52 >= 50 floats)
__global__ __launch_bounds__(256) void edge1_kernel(const int* __restrict__ ei) {
    int t = blockIdx.x * blockDim.x + threadIdx.x;
    int e = t >> 4;
    if (e >= NE) return;
    int l = t & 15;
    size_t s = (size_t)ei[e], d = (size_t)ei[NE + e];
    if (l < 13) {
        float4 v = *(const float4*)(g_xpad + s * XP + l * 4);
        red4(g_agg1 + d * XP + l * 4, v);
    } else if (l == 13) {
        atomicAdd(g_deg + d, 1.0f);
    }
}

// ---------------- layer-1 fused GEMM + L2-normalize + ELU -------------------
// block = 256 threads (one per output column), 16 rows per block
__global__ __launch_bounds__(256) void gemm1_kernel(
    const float* __restrict__ x,
    const float* __restrict__ w1l, const float* __restrict__ b1,
    const float* __restrict__ w1r,
    const float* __restrict__ wl1, const float* __restrict__ bl1)
{
    __shared__ __align__(16) float sm[16][64];   // mean rows
    __shared__ __align__(16) float sx[16][64];   // x rows
    __shared__ float sinv[16];
    __shared__ float spart[16][8];

    int j = threadIdx.x;
    int row0 = blockIdx.x * 16;

    if (j < 16) sinv[j] = 1.f / fmaxf(g_deg[row0 + j], 1.f);
    __syncthreads();

    for (int i = j; i < 16 * 52; i += 256) {
        int r = i / 52, c = i % 52;
        int row = row0 + r;
        sm[r][c] = (c < IND) ? g_agg1[(size_t)row * XP + c] * sinv[r] : 0.f;
        sx[r][c] = (c < IND) ? x[(size_t)row * IND + c] : 0.f;
    }
    __syncthreads();

    float acc[16], lin[16];
    float bj = b1[j], blj = bl1[j];
#pragma unroll
    for (int r = 0; r < 16; r++) { acc[r] = bj; lin[r] = blj; }

#pragma unroll 2
    for (int k = 0; k < 48; k += 4) {
        float wa0 = w1l[(k+0)*HID + j], wa1 = w1l[(k+1)*HID + j];
        float wa2 = w1l[(k+2)*HID + j], wa3 = w1l[(k+3)*HID + j];
        float wb0 = w1r[(k+0)*HID + j], wb1 = w1r[(k+1)*HID + j];
        float wb2 = w1r[(k+2)*HID + j], wb3 = w1r[(k+3)*HID + j];
        float wc0 = wl1[(k+0)*HID + j], wc1 = wl1[(k+1)*HID + j];
        float wc2 = wl1[(k+2)*HID + j], wc3 = wl1[(k+3)*HID + j];
#pragma unroll
        for (int r = 0; r < 16; r++) {
            float4 m  = *(const float4*)&sm[r][k];
            float4 xv = *(const float4*)&sx[r][k];
            acc[r] += m.x*wa0 + m.y*wa1 + m.z*wa2 + m.w*wa3
                    + xv.x*wb0 + xv.y*wb1 + xv.z*wb2 + xv.w*wb3;
            lin[r] += xv.x*wc0 + xv.y*wc1 + xv.z*wc2 + xv.w*wc3;
        }
    }
    for (int k = 48; k < 50; k++) {
        float wa = w1l[k*HID + j], wb = w1r[k*HID + j], wc = wl1[k*HID + j];
#pragma unroll
        for (int r = 0; r < 16; r++) {
            acc[r] += sm[r][k] * wa + sx[r][k] * wb;
            lin[r] += sx[r][k] * wc;
        }
    }

    int lane = j & 31, warp = j >> 5;
#pragma unroll
    for (int r = 0; r < 16; r++) {
        float v = acc[r] * acc[r];
#pragma unroll
        for (int o = 16; o; o >>= 1) v += __shfl_xor_sync(0xffffffffu, v, o);
        if (lane == 0) spart[r][warp] = v;
    }
    __syncthreads();
#pragma unroll
    for (int r = 0; r < 16; r++) {
        float s = 0.f;
#pragma unroll
        for (int w = 0; w < 8; w++) s += spart[r][w];
        float inv = 1.f / fmaxf(sqrtf(s), 1e-12f);
        float z = acc[r] * inv + lin[r];
        g_h[(size_t)(row0 + r) * HID + j] = (z > 0.f) ? z : expm1f(z);  // ELU
    }
}

// ---------------- layer-2 GEMM: [p | r | l2] = h @ [w2_l | w2_r | wl2] ------
// block = 384 threads (one per combined column), 16 rows per block
__global__ __launch_bounds__(384) void gemm2_kernel(
    const float* __restrict__ w2l, const float* __restrict__ w2r,
    const float* __restrict__ wl2)
{
    __shared__ __align__(16) float sa[16][HID];
    int j = threadIdx.x;
    int row0 = blockIdx.x * 16;

    for (int i = j; i < 16 * (HID / 4); i += 384) {
        int r = i >> 6, c4 = i & 63;
        ((float4*)sa[r])[c4] = ((const float4*)(g_h + (size_t)(row0 + r) * HID))[c4];
    }
    __syncthreads();

    const float* wcol = nullptr; int slot = -1;
    if      (j < NC)     { wcol = w2l + j;          slot = j;      }  // p: 0..120
    else if (j < 2*NC)   { wcol = w2r + (j - NC);   slot = j + 7;  }  // r: 128..248
    else if (j < 3*NC)   { wcol = wl2 + (j - 2*NC); slot = j + 14; }  // l2: 256..376

    float acc[16];
#pragma unroll
    for (int r = 0; r < 16; r++) acc[r] = 0.f;

    if (wcol) {
#pragma unroll 2
        for (int k = 0; k < HID; k += 4) {
            float w0 = wcol[(k+0)*NC], w1 = wcol[(k+1)*NC];
            float w2 = wcol[(k+2)*NC], w3 = wcol[(k+3)*NC];
#pragma unroll
            for (int r = 0; r < 16; r++) {
                float4 a = *(const float4*)&sa[r][k];
                acc[r] += a.x*w0 + a.y*w1 + a.z*w2 + a.w*w3;
            }
        }
#pragma unroll
        for (int r = 0; r < 16; r++)
            g_prl[(size_t)(row0 + r) * PRLS + slot] = acc[r];
    }
}

// ---------------- edge scatter 2: aggp += p[src] ----------------------------
// warp per edge; lanes 0..30 move 31 float4 (124 >= 121 floats; pad cols are 0)
__global__ __launch_bounds__(256) void edge2_kernel(const int* __restrict__ ei) {
    int t = blockIdx.x * blockDim.x + threadIdx.x;
    int e = t >> 5;
    if (e >= NE) return;
    int l = t & 31;
    if (l >= 31) return;
    size_t s = (size_t)ei[e], d = (size_t)ei[NE + e];
    float4 v = *(const float4*)(g_prl + s * PRLS + l * 4);
    red4(g_aggp + d * AGP + l * 4, v);
}

// ---------------- final: normalize(aggp/deg + b2 + r) + l2 + bl2 ------------
// block = 128 threads (j < 121 active), 8 rows per block
__global__ __launch_bounds__(128) void final_kernel(
    const float* __restrict__ b2, const float* __restrict__ bl2,
    float* __restrict__ out)
{
    __shared__ float part[4];
    int j = threadIdx.x;
    int lane = j & 31, warp = j >> 5;
    int row0 = blockIdx.x * 8;
    float b2j  = (j < NC) ? b2[j]  : 0.f;
    float bl2j = (j < NC) ? bl2[j] : 0.f;

    for (int r = 0; r < 8; r++) {
        int row = row0 + r;
        float invd = 1.f / fmaxf(g_deg[row], 1.f);
        float tv = 0.f, l2v = 0.f;
        if (j < NC) {
            tv  = g_aggp[(size_t)row * AGP + j] * invd + b2j
                + g_prl[(size_t)row * PRLS + 128 + j];
            l2v = g_prl[(size_t)row * PRLS + 256 + j] + bl2j;
        }
        float v = tv * tv;
#pragma unroll
        for (int o = 16; o; o >>= 1) v += __shfl_xor_sync(0xffffffffu, v, o);
        if (lane == 0) part[warp] = v;
        __syncthreads();
        float s = part[0] + part[1] + part[2] + part[3];
        float inv = 1.f / fmaxf(sqrtf(s), 1e-12f);
        if (j < NC) out[(size_t)row * NC + j] = tv * inv + l2v;
        __syncthreads();
    }
}

// ---------------- launcher ---------------------------------------------------
extern "C" void kernel_launch(void* const* d_in, const int* in_sizes, int n_in,
                              void* d_out, int out_size)
{
    const float* x   = (const float*)d_in[0];
    const int*   ei  = (const int*)d_in[1];       // int32 on device (JAX x64 off)
    const float* w1l = (const float*)d_in[2];
    const float* b1  = (const float*)d_in[3];
    const float* w1r = (const float*)d_in[4];
    const float* wl1 = (const float*)d_in[5];
    const float* bl1 = (const float*)d_in[6];
    const float* w2l = (const float*)d_in[7];
    const float* b2  = (const float*)d_in[8];
    const float* w2r = (const float*)d_in[9];
    const float* wl2 = (const float*)d_in[10];
    const float* bl2 = (const float*)d_in[11];
    float* out = (float*)d_out;

    zero_all_kernel<<<6250, 256>>>();
    pad_x_kernel  <<<(NN * XP) / 256, 256>>>(x);
    edge1_kernel  <<<(NE * 16) / 256, 256>>>(ei);
    gemm1_kernel  <<<NN / 16, 256>>>(x, w1l, b1, w1r, wl1, bl1);
    gemm2_kernel  <<<NN / 16, 384>>>(w2l, w2r, wl2);
    edge2_kernel  <<<(NE * 32) / 256, 256>>>(ei);
    final_kernel  <<<NN / 8, 128>>>(b2, bl2, out);
}